// round 1
// baseline (speedup 1.0000x reference)
#include <cuda_runtime.h>
#include <math_constants.h>

// NearestEmbed: x (64,256,32,32) f32, emb (256,1024) f32
// out = gather of nearest code per latent, back to (B,D,H,W); plus argmin (B,H,W)
// score[n,k] = ||e_k||^2 - 2 * x_n . e_k   (||x||^2 constant per row, dropped)

#define D_DIM 256
#define K_DIM 1024
#define BM 128
#define BN 128
#define BD 32

__device__ float g_e2[K_DIM];

__global__ void e2_kernel(const float* __restrict__ emb) {
    int k = blockIdx.x * blockDim.x + threadIdx.x;  // 1024 threads total
    float s = 0.f;
#pragma unroll 8
    for (int d = 0; d < D_DIM; ++d) {
        float v = emb[(size_t)d * K_DIM + k];
        s = fmaf(v, v, s);
    }
    g_e2[k] = s;
}

__device__ __forceinline__ unsigned long long pack2(float v) {
    unsigned long long r;
    unsigned int u = __float_as_uint(v);
    asm("mov.b64 %0, {%1, %1};" : "=l"(r) : "r"(u));
    return r;
}

// packed dual-fp32 FMA (Blackwell FFMA2) — only reachable via PTX f32x2
__device__ __forceinline__ void ffma2(unsigned long long& c,
                                      unsigned long long a,
                                      unsigned long long b) {
    asm("fma.rn.f32x2 %0, %1, %2, %0;" : "+l"(c) : "l"(a), "l"(b));
}

__global__ __launch_bounds__(256, 2)
void vq_kernel(const float* __restrict__ x, const float* __restrict__ emb,
               float* __restrict__ out, float* __restrict__ idx_out, int has_idx) {
    __shared__ float xs[BD][BM];
    __shared__ float es[BD][BN];
    __shared__ float red_val[BM][16];
    __shared__ int   red_idx[BM][16];
    __shared__ int   idx_s[BM];

    const int tid = threadIdx.x;
    const int tm = tid & 15;   // latent sub-tile 0..15 (8 rows each)
    const int tn = tid >> 4;   // code   sub-tile 0..15 (8 cols each)
    const int n0 = blockIdx.x * BM;      // 512 blocks; 128 latents each
    const int b = n0 >> 10;              // latents 0..1023 within one batch image
    const int hw0 = n0 & 1023;
    const float* xbase = x + (size_t)b * D_DIM * 1024 + hw0;

    float best[8];
    int   bidx[8];
#pragma unroll
    for (int i = 0; i < 8; ++i) { best[i] = CUDART_INF_F; bidx[i] = 0; }

    for (int kt = 0; kt < K_DIM / BN; ++kt) {
        const int k0 = kt * BN;
        unsigned long long acc[8][4];  // 8 latents x 8 codes, packed pairs along code dim
#pragma unroll
        for (int i = 0; i < 8; ++i)
#pragma unroll
            for (int j = 0; j < 4; ++j) acc[i][j] = 0ull;

        for (int dt = 0; dt < D_DIM; dt += BD) {
            // cooperative load: 32 rows x 128 floats each for x and e (coalesced float4)
#pragma unroll
            for (int p = 0; p < 4; ++p) {
                int f = tid + p * 256;      // float4 slot 0..1023
                int row = f >> 5;
                int c4 = (f & 31) << 2;
                *(float4*)&xs[row][c4] =
                    *(const float4*)(xbase + (size_t)(dt + row) * 1024 + c4);
                *(float4*)&es[row][c4] =
                    *(const float4*)(emb + (size_t)(dt + row) * K_DIM + k0 + c4);
            }
            __syncthreads();
#pragma unroll 8
            for (int d = 0; d < BD; ++d) {
                float4 a0 = *(const float4*)&xs[d][tm * 8];
                float4 a1 = *(const float4*)&xs[d][tm * 8 + 4];
                ulonglong2 bb0 = *(const ulonglong2*)&es[d][tn * 8];
                ulonglong2 bb1 = *(const ulonglong2*)&es[d][tn * 8 + 4];
                unsigned long long bp[4] = {bb0.x, bb0.y, bb1.x, bb1.y};
                float av[8] = {a0.x, a0.y, a0.z, a0.w, a1.x, a1.y, a1.z, a1.w};
#pragma unroll
                for (int i = 0; i < 8; ++i) {
                    unsigned long long ap = pack2(av[i]);
#pragma unroll
                    for (int j = 0; j < 4; ++j) ffma2(acc[i][j], ap, bp[j]);
                }
            }
            __syncthreads();
        }

        // fused argmin epilogue for this code tile (ascending idx -> first-min tie rule)
        float e2v[8];
#pragma unroll
        for (int jj = 0; jj < 8; ++jj) e2v[jj] = g_e2[k0 + tn * 8 + jj];
#pragma unroll
        for (int i = 0; i < 8; ++i) {
#pragma unroll
            for (int j = 0; j < 4; ++j) {
                unsigned int lo = (unsigned int)acc[i][j];
                unsigned int hi = (unsigned int)(acc[i][j] >> 32);
                float s0 = fmaf(-2.f, __uint_as_float(lo), e2v[2 * j]);
                float s1 = fmaf(-2.f, __uint_as_float(hi), e2v[2 * j + 1]);
                int kk = k0 + tn * 8 + 2 * j;
                if (s0 < best[i]) { best[i] = s0; bidx[i] = kk; }
                if (s1 < best[i]) { best[i] = s1; bidx[i] = kk + 1; }
            }
        }
    }

    // cross-thread reduction: 16 code-subtile owners per latent row
#pragma unroll
    for (int i = 0; i < 8; ++i) {
        red_val[tm * 8 + i][tn] = best[i];
        red_idx[tm * 8 + i][tn] = bidx[i];
    }
    __syncthreads();
    if (tid < BM) {
        float bv = red_val[tid][0];
        int bi = red_idx[tid][0];
#pragma unroll
        for (int t = 1; t < 16; ++t) {
            float v = red_val[tid][t];
            int id = red_idx[tid][t];
            if (v < bv || (v == bv && id < bi)) { bv = v; bi = id; }
        }
        idx_s[tid] = bi;
        if (has_idx) idx_out[n0 + tid] = (float)bi;
    }
    __syncthreads();

    // gather nearest code and scatter back to (B,D,H,W); writes coalesced along HW
    for (int r = tid; r < D_DIM * BM; r += 256) {
        int d = r >> 7;
        int m = r & (BM - 1);
        out[((size_t)b * D_DIM + d) * 1024 + hw0 + m] =
            emb[(size_t)d * K_DIM + idx_s[m]];
    }
}

extern "C" void kernel_launch(void* const* d_in, const int* in_sizes, int n_in,
                              void* d_out, int out_size) {
    const float* x = (const float*)d_in[0];    // (64,256,32,32)
    const float* emb = (const float*)d_in[1];  // (256,1024)
    float* out = (float*)d_out;

    const int n_img = 64 * 256 * 32 * 32;      // 16777216
    const int n_lat = 64 * 32 * 32;            // 65536
    float* idx_out = nullptr;
    int has_idx = 0;
    if (out_size >= n_img + n_lat) {           // tuple output: (out, argmin)
        idx_out = out + n_img;
        has_idx = 1;
    }

    e2_kernel<<<4, 256>>>(emb);
    vq_kernel<<<512, 256>>>(x, emb, out, idx_out, has_idx);
}